// round 16
// baseline (speedup 1.0000x reference)
#include <cuda_runtime.h>
#include <math.h>
#include <stdint.h>

// ---------------- problem constants ----------------
constexpr int BATCH = 16;
constexpr int L     = 256;      // H*W
constexpr int DIM   = 768;
constexpr int NH    = 8;
constexpr int HD    = 96;
constexpr int NEXP  = 8;
constexpr int EB    = NEXP * BATCH;   // 128 (expert, batch) pairs
constexpr float SCALE = 0.102062072615966f; // 1/sqrt(96)

// ---------------- device scratch (static; no allocation) ----------------
__device__ float g_qkv   [BATCH * L * 3 * DIM];
__device__ float g_ctx   [BATCH * L * DIM];
__device__ float g_k2    [NEXP * DIM];
__device__ float g_u     [64 * DIM];
__device__ float g_qvec  [64 * DIM];
__device__ float g_const [64];
__device__ float g_aw    [BATCH * L * NEXP];
__device__ float g_wsel  [EB];
__device__ float g_xz    [EB * L * 2 * DIM];
__device__ float g_xc    [EB * L * DIM];
__device__ float g_dbl   [EB * 4 * L * 6];
__device__ float g_y     [(size_t)EB * L * DIM];

// ---------------- helpers ----------------
__device__ __forceinline__ float siluf(float x) { return x / (1.f + __expf(-x)); }
__device__ __forceinline__ float softplusf(float x) {
    return (x > 20.f) ? x : __logf(1.f + __expf(x));
}
__device__ __forceinline__ int dirmap(int dir, int t) {
    int tt = (dir & 1) ? (L - 1 - t) : t;
    if (dir < 2) return tt;
    return ((tt & 15) << 4) | (tt >> 4);
}
__device__ __forceinline__ uint32_t f2tf32(float f) {
    uint32_t u;
    asm("cvt.rna.tf32.f32 %0, %1;" : "=r"(u) : "f"(f));
    return u;
}
__device__ __forceinline__ void mma_tf32(float* c, uint32_t a0, uint32_t a1,
                                         uint32_t a2, uint32_t a3,
                                         uint32_t b0, uint32_t b1) {
    asm volatile(
        "mma.sync.aligned.m16n8k8.row.col.f32.tf32.tf32.f32 "
        "{%0,%1,%2,%3}, {%4,%5,%6,%7}, {%8,%9}, {%0,%1,%2,%3};"
        : "+f"(c[0]), "+f"(c[1]), "+f"(c[2]), "+f"(c[3])
        : "r"(a0), "r"(a1), "r"(a2), "r"(a3), "r"(b0), "r"(b1));
}
__device__ __forceinline__ void cp_async16(void* sptr, const void* gptr) {
    uint32_t s = (uint32_t)__cvta_generic_to_shared(sptr);
    asm volatile("cp.async.cg.shared.global [%0], [%1], 16;" :: "r"(s), "l"(gptr));
}

// ------- tf32 128x128 GEMM: cp.async double-buffer, 32-k stages -------
// Each stage holds two 16-k groups in verified conflict-free pitch-20 layout.
__device__ __forceinline__ void gemm128_tf32(const float* __restrict__ A,
                                             const float* __restrict__ Wt,
                                             const float* __restrict__ bias,
                                             float* __restrict__ C,
                                             int K, int ldc) {
    __shared__ float As[2][2][128][20];
    __shared__ float Bs[2][2][128][20];

    const int tid  = threadIdx.x;
    const int wid  = tid >> 5, lane = tid & 31;
    const int mw   = wid & 1, nw = wid >> 1;
    const int m0   = mw * 64, n0 = nw * 32;
    const int r    = lane >> 2, c4 = lane & 3;
    const int lrow0 = tid >> 2;
    const int lrow1 = lrow0 + 64;
    const int lkc   = (tid & 3) << 2;

    float acc[4][4][4];
#pragma unroll
    for (int i = 0; i < 4; i++)
#pragma unroll
        for (int j = 0; j < 4; j++)
#pragma unroll
            for (int q = 0; q < 4; q++) acc[i][j][q] = 0.f;

    // prologue: stage 0 (k = 0..31)
#pragma unroll
    for (int g = 0; g < 2; g++) {
        int kg = g * 16 + lkc;
        cp_async16(&As[0][g][lrow0][lkc], &A [(size_t)lrow0 * K + kg]);
        cp_async16(&As[0][g][lrow1][lkc], &A [(size_t)lrow1 * K + kg]);
        cp_async16(&Bs[0][g][lrow0][lkc], &Wt[(size_t)lrow0 * K + kg]);
        cp_async16(&Bs[0][g][lrow1][lkc], &Wt[(size_t)lrow1 * K + kg]);
    }
    asm volatile("cp.async.commit_group;");

    int buf = 0;
    for (int k0 = 32; k0 <= K; k0 += 32) {
        asm volatile("cp.async.wait_group 0;");
        __syncthreads();
        if (k0 < K) {
            int nb = buf ^ 1;
#pragma unroll
            for (int g = 0; g < 2; g++) {
                int kg = k0 + g * 16 + lkc;
                cp_async16(&As[nb][g][lrow0][lkc], &A [(size_t)lrow0 * K + kg]);
                cp_async16(&As[nb][g][lrow1][lkc], &A [(size_t)lrow1 * K + kg]);
                cp_async16(&Bs[nb][g][lrow0][lkc], &Wt[(size_t)lrow0 * K + kg]);
                cp_async16(&Bs[nb][g][lrow1][lkc], &Wt[(size_t)lrow1 * K + kg]);
            }
            asm volatile("cp.async.commit_group;");
        }
#pragma unroll
        for (int g = 0; g < 2; g++) {
#pragma unroll
            for (int kk = 0; kk < 16; kk += 8) {
                uint32_t bf0[4], bf1[4];
#pragma unroll
                for (int fn = 0; fn < 4; fn++) {
                    bf0[fn] = f2tf32(Bs[buf][g][n0 + fn * 8 + r][kk + c4]);
                    bf1[fn] = f2tf32(Bs[buf][g][n0 + fn * 8 + r][kk + 4 + c4]);
                }
#pragma unroll
                for (int fm = 0; fm < 4; fm++) {
                    uint32_t a0 = f2tf32(As[buf][g][m0 + fm * 16 + r    ][kk + c4]);
                    uint32_t a1 = f2tf32(As[buf][g][m0 + fm * 16 + r + 8][kk + c4]);
                    uint32_t a2 = f2tf32(As[buf][g][m0 + fm * 16 + r    ][kk + 4 + c4]);
                    uint32_t a3 = f2tf32(As[buf][g][m0 + fm * 16 + r + 8][kk + 4 + c4]);
#pragma unroll
                    for (int fn = 0; fn < 4; fn++)
                        mma_tf32(acc[fm][fn], a0, a1, a2, a3, bf0[fn], bf1[fn]);
                }
            }
        }
        buf ^= 1;
    }

#pragma unroll
    for (int fm = 0; fm < 4; fm++) {
#pragma unroll
        for (int fn = 0; fn < 4; fn++) {
            int rl = m0 + fm * 16 + r;
            int cl = n0 + fn * 8 + (lane & 3) * 2;
            float2 v0, v1;
            v0.x = acc[fm][fn][0] + bias[cl];
            v0.y = acc[fm][fn][1] + bias[cl + 1];
            v1.x = acc[fm][fn][2] + bias[cl];
            v1.y = acc[fm][fn][3] + bias[cl + 1];
            *(float2*)&C[(size_t)rl * ldc + cl]       = v0;
            *(float2*)&C[(size_t)(rl + 8) * ldc + cl] = v1;
        }
    }
}

__global__ void __launch_bounds__(256, 2)
gemm_tf32_plain(const float* __restrict__ A, const float* __restrict__ Wt,
                const float* __restrict__ bias, float* __restrict__ C, int K, int N) {
    gemm128_tf32(A + (size_t)blockIdx.y * 128 * K,
                 Wt + (size_t)blockIdx.x * 128 * K,
                 bias + blockIdx.x * 128,
                 C + (size_t)blockIdx.y * 128 * N + blockIdx.x * 128, K, N);
}

__global__ void __launch_bounds__(256, 2)
gemm_xz_tf32(const float* __restrict__ x, const float* __restrict__ ew,
             const float* __restrict__ eb) {
    int z = blockIdx.z;
    if (g_wsel[z] == 0.f) return;
    int e = z >> 4, b = z & 15;
    gemm128_tf32(x + ((size_t)b * L + blockIdx.y * 128) * DIM,
                 ew + ((size_t)e * 2 * DIM + blockIdx.x * 128) * DIM,
                 eb + e * 2 * DIM + blockIdx.x * 128,
                 g_xz + (size_t)z * L * 2 * DIM
                      + (size_t)blockIdx.y * 128 * 2 * DIM + blockIdx.x * 128,
                 DIM, 2 * DIM);
}

// ---- flash-style tf32 attention: 64-query tiles (unchanged) ----
constexpr int ATTN_SMEM = (6400 + 6400 + 6528 + 4352 + 64) * 4;

__global__ void __launch_bounds__(256) attn_kernel() {
    const int h = blockIdx.x, b = blockIdx.y, qt = blockIdx.z;
    extern __shared__ float sm[];
    uint32_t* Qs  = (uint32_t*)sm;
    uint32_t* Ks  = (uint32_t*)(sm + 6400);
    uint32_t* Vt  = (uint32_t*)(sm + 12800);
    float*    Ps  = sm + 19328;
    uint32_t* Psu = (uint32_t*)Ps;
    float*    rsum = sm + 23680;

    const int tid = threadIdx.x;
    const int wid = tid >> 5, lane = tid & 31;
    const int r = lane >> 2;
    const int m0 = (wid & 1) * 32;
    const int nw = wid >> 1;
    const int n1 = nw * 16;
    const int n2 = nw * 24;

    const float* base = g_qkv + (size_t)b * L * 3 * DIM;

    for (int i = tid; i < 64 * 24; i += 256) {
        int row = i / 24, p = (i % 24) * 4;
        float4 v = *(const float4*)&base[(size_t)(qt * 64 + row) * 3 * DIM + h * HD + p];
        uint32_t* d = &Qs[row * 100 + p];
        d[0] = f2tf32(v.x); d[1] = f2tf32(v.y); d[2] = f2tf32(v.z); d[3] = f2tf32(v.w);
    }
    if (tid < 64) rsum[tid] = 0.f;

    float acc2[2][3][4];
#pragma unroll
    for (int i = 0; i < 2; i++)
#pragma unroll
        for (int j = 0; j < 3; j++)
#pragma unroll
            for (int q = 0; q < 4; q++) acc2[i][j][q] = 0.f;

    for (int kt = 0; kt < 4; kt++) {
        __syncthreads();
        for (int i = tid; i < 64 * 24; i += 256) {
            int row = i / 24, p = (i % 24) * 4;
            float4 v = *(const float4*)&base[(size_t)(kt * 64 + row) * 3 * DIM + DIM + h * HD + p];
            uint32_t* d = &Ks[row * 100 + p];
            d[0] = f2tf32(v.x); d[1] = f2tf32(v.y); d[2] = f2tf32(v.z); d[3] = f2tf32(v.w);
        }
        for (int i = tid; i < 64 * 96; i += 256) {
            int key = i / 96, d = i % 96;
            float v = base[(size_t)(kt * 64 + key) * 3 * DIM + 2 * DIM + h * HD + d];
            Vt[d * 68 + key] = f2tf32(v);
        }
        __syncthreads();

        float acc1[2][2][4];
#pragma unroll
        for (int i = 0; i < 2; i++)
#pragma unroll
            for (int j = 0; j < 2; j++)
#pragma unroll
                for (int q = 0; q < 4; q++) acc1[i][j][q] = 0.f;

        for (int kk = 0; kk < 96; kk += 8) {
            uint32_t bf0[2], bf1[2];
#pragma unroll
            for (int fn = 0; fn < 2; fn++) {
                bf0[fn] = Ks[(n1 + fn * 8 + r) * 100 + kk + (lane & 3)];
                bf1[fn] = Ks[(n1 + fn * 8 + r) * 100 + kk + 4 + (lane & 3)];
            }
#pragma unroll
            for (int fm = 0; fm < 2; fm++) {
                uint32_t a0 = Qs[(m0 + fm * 16 + r    ) * 100 + kk + (lane & 3)];
                uint32_t a1 = Qs[(m0 + fm * 16 + r + 8) * 100 + kk + (lane & 3)];
                uint32_t a2 = Qs[(m0 + fm * 16 + r    ) * 100 + kk + 4 + (lane & 3)];
                uint32_t a3 = Qs[(m0 + fm * 16 + r + 8) * 100 + kk + 4 + (lane & 3)];
#pragma unroll
                for (int fn = 0; fn < 2; fn++)
                    mma_tf32(acc1[fm][fn], a0, a1, a2, a3, bf0[fn], bf1[fn]);
            }
        }
#pragma unroll
        for (int fm = 0; fm < 2; fm++) {
#pragma unroll
            for (int fn = 0; fn < 2; fn++) {
                int rl = m0 + fm * 16 + r;
                int cl = n1 + fn * 8 + (lane & 3) * 2;
                Psu[rl * 68 + cl]           = f2tf32(__expf(acc1[fm][fn][0] * SCALE));
                Psu[rl * 68 + cl + 1]       = f2tf32(__expf(acc1[fm][fn][1] * SCALE));
                Psu[(rl + 8) * 68 + cl]     = f2tf32(__expf(acc1[fm][fn][2] * SCALE));
                Psu[(rl + 8) * 68 + cl + 1] = f2tf32(__expf(acc1[fm][fn][3] * SCALE));
            }
        }
        __syncthreads();
        if (tid < 64) {
            float s = 0.f;
            const float* pr = &Ps[tid * 68];
#pragma unroll 8
            for (int k = 0; k < 64; k++) s += pr[k];
            rsum[tid] += s;
        }
        for (int kk = 0; kk < 64; kk += 8) {
            uint32_t bf0[3], bf1[3];
#pragma unroll
            for (int fn = 0; fn < 3; fn++) {
                bf0[fn] = Vt[(n2 + fn * 8 + r) * 68 + kk + (lane & 3)];
                bf1[fn] = Vt[(n2 + fn * 8 + r) * 68 + kk + 4 + (lane & 3)];
            }
#pragma unroll
            for (int fm = 0; fm < 2; fm++) {
                uint32_t a0 = Psu[(m0 + fm * 16 + r    ) * 68 + kk + (lane & 3)];
                uint32_t a1 = Psu[(m0 + fm * 16 + r + 8) * 68 + kk + (lane & 3)];
                uint32_t a2 = Psu[(m0 + fm * 16 + r    ) * 68 + kk + 4 + (lane & 3)];
                uint32_t a3 = Psu[(m0 + fm * 16 + r + 8) * 68 + kk + 4 + (lane & 3)];
#pragma unroll
                for (int fn = 0; fn < 3; fn++)
                    mma_tf32(acc2[fm][fn], a0, a1, a2, a3, bf0[fn], bf1[fn]);
            }
        }
    }
    __syncthreads();

#pragma unroll
    for (int fm = 0; fm < 2; fm++) {
        int rl = m0 + fm * 16 + r;
        float inv0 = 1.f / rsum[rl];
        float inv1 = 1.f / rsum[rl + 8];
        int q0 = qt * 64 + rl;
#pragma unroll
        for (int fn = 0; fn < 3; fn++) {
            int cl = n2 + fn * 8 + (lane & 3) * 2;
            float* o0 = &g_ctx[((size_t)b * L + q0) * DIM + h * HD + cl];
            float* o1 = &g_ctx[((size_t)b * L + q0 + 8) * DIM + h * HD + cl];
            o0[0] = acc2[fm][fn][0] * inv0;
            o0[1] = acc2[fm][fn][1] * inv0;
            o1[0] = acc2[fm][fn][2] * inv1;
            o1[1] = acc2[fm][fn][3] * inv1;
        }
    }
}

// ---- gating precompute: warp-distributed k2 + coalesced u; grid (64, 3) ----
__global__ void __launch_bounds__(256)
gating_pre(const float* __restrict__ eq, const float* __restrict__ ca_w,
           const float* __restrict__ ca_b) {
    int he = blockIdx.x;
    int e = he & 7, h = he >> 3;
    int tid = threadIdx.x;
    int wid = tid >> 5, lane = tid & 31;
    __shared__ float eqs[DIM];
    __shared__ float k2s[HD];

    for (int i = tid; i < DIM; i += 256) eqs[i] = eq[e * DIM + i];
    __syncthreads();

#pragma unroll
    for (int j = 0; j < 12; j++) {
        int d = wid * 12 + j;
        int c = h * HD + d;
        const float* w = ca_w + (size_t)(DIM + c) * DIM;
        float s = 0.f;
#pragma unroll
        for (int k = lane * 4; k < DIM; k += 128) {
            float4 wv = *(const float4*)&w[k];
            s += eqs[k] * wv.x + eqs[k + 1] * wv.y + eqs[k + 2] * wv.z + eqs[k + 3] * wv.w;
        }
#pragma unroll
        for (int o = 16; o; o >>= 1) s += __shfl_xor_sync(0xffffffffu, s, o);
        if (lane == 0) k2s[d] = s + ca_b[DIM + c];
    }
    __syncthreads();

    if (blockIdx.y == 0 && tid < HD) g_k2[e * DIM + h * HD + tid] = k2s[tid];

    int c = blockIdx.y * 256 + tid;
    float s = 0.f;
#pragma unroll 4
    for (int d = 0; d < HD; d++) s += ca_w[(size_t)(h * HD + d) * DIM + c] * k2s[d];
    g_u[(size_t)he * DIM + c] = s;
}

__global__ void __launch_bounds__(256)
vqc_kernel(const float* __restrict__ ca_b, const float* __restrict__ sa_ob) {
    int he = blockIdx.x;
    int e = he & 7, h = he >> 3;
    int tid = threadIdx.x;
    __shared__ float red[256];
    float part = 0.f;
    for (int c = tid; c < DIM; c += 256) part += sa_ob[c] * g_u[(size_t)he * DIM + c];
    if (tid < HD) part += ca_b[h * HD + tid] * g_k2[e * DIM + h * HD + tid];
    red[tid] = part;
    __syncthreads();
    for (int s = 128; s; s >>= 1) {
        if (tid < s) red[tid] += red[tid + s];
        __syncthreads();
    }
    if (tid == 0) g_const[he] = red[0];
}

__global__ void __launch_bounds__(256)
vq2_kernel(const float* __restrict__ sa_ow) {
    __shared__ float Us[16][68];
    __shared__ float Ws[16][68];
    const int tid = threadIdx.x;
    const int tx = tid & 15, ty = tid >> 4;
    const int n0 = blockIdx.x * 64;
    const int row = tid >> 2, kc = (tid & 3) << 2;

    float acc[4][4];
#pragma unroll
    for (int i = 0; i < 4; i++)
#pragma unroll
        for (int j = 0; j < 4; j++) acc[i][j] = 0.f;

    for (int k0 = 0; k0 < DIM; k0 += 16) {
        float4 vu = *(const float4*)&g_u[(size_t)row * DIM + k0 + kc];
        Us[kc + 0][row] = vu.x; Us[kc + 1][row] = vu.y;
        Us[kc + 2][row] = vu.z; Us[kc + 3][row] = vu.w;
        int wk = tid >> 4, wc = (tid & 15) * 4;
        float4 vw = *(const float4*)&sa_ow[(size_t)(k0 + wk) * DIM + n0 + wc];
        Ws[wk][wc + 0] = vw.x; Ws[wk][wc + 1] = vw.y;
        Ws[wk][wc + 2] = vw.z; Ws[wk][wc + 3] = vw.w;
        __syncthreads();
#pragma unroll
        for (int k = 0; k < 16; k++) {
            float a[4], w[4];
            *(float4*)&a[0] = *(const float4*)&Us[k][ty * 4];
            *(float4*)&w[0] = *(const float4*)&Ws[k][tx * 4];
#pragma unroll
            for (int i = 0; i < 4; i++)
#pragma unroll
                for (int j = 0; j < 4; j++) acc[i][j] += a[i] * w[j];
        }
        __syncthreads();
    }
#pragma unroll
    for (int i = 0; i < 4; i++)
#pragma unroll
        for (int j = 0; j < 4; j++)
            g_qvec[(size_t)(ty * 4 + i) * DIM + n0 + tx * 4 + j] = acc[i][j];
}

// scores + per-token softmax over experts + head-mean, fused
__global__ void __launch_bounds__(256)
scores_kernel() {
    __shared__ float As[16][68];
    __shared__ float Qs[16][68];
    __shared__ float Sb[64][65];
    const int tid = threadIdx.x;
    const int tx = tid & 15, ty = tid >> 4;
    const int row = tid >> 2, kc = (tid & 3) << 2;
    const float* A = g_ctx + (size_t)blockIdx.x * 64 * DIM;

    float acc[4][4];
#pragma unroll
    for (int i = 0; i < 4; i++)
#pragma unroll
        for (int j = 0; j < 4; j++) acc[i][j] = 0.f;

    for (int k0 = 0; k0 < DIM; k0 += 16) {
        float4 va = *(const float4*)&A[(size_t)row * DIM + k0 + kc];
        float4 vq = *(const float4*)&g_qvec[(size_t)row * DIM + k0 + kc];
        As[kc + 0][row] = va.x; As[kc + 1][row] = va.y;
        As[kc + 2][row] = va.z; As[kc + 3][row] = va.w;
        Qs[kc + 0][row] = vq.x; Qs[kc + 1][row] = vq.y;
        Qs[kc + 2][row] = vq.z; Qs[kc + 3][row] = vq.w;
        __syncthreads();
#pragma unroll
        for (int k = 0; k < 16; k++) {
            float a[4], q[4];
            *(float4*)&a[0] = *(const float4*)&As[k][ty * 4];
            *(float4*)&q[0] = *(const float4*)&Qs[k][tx * 4];
#pragma unroll
            for (int i = 0; i < 4; i++)
#pragma unroll
                for (int j = 0; j < 4; j++) acc[i][j] += a[i] * q[j];
        }
        __syncthreads();
    }
#pragma unroll
    for (int i = 0; i < 4; i++)
#pragma unroll
        for (int j = 0; j < 4; j++)
            Sb[ty * 4 + i][tx * 4 + j] = (acc[i][j] + g_const[tx * 4 + j]) * SCALE;
    __syncthreads();

    if (tid < 64) {
        float aw[8];
#pragma unroll
        for (int e = 0; e < 8; e++) aw[e] = 0.f;
        for (int h = 0; h < 8; h++) {
            float v[8], mx = -1e30f;
#pragma unroll
            for (int e = 0; e < 8; e++) { v[e] = Sb[tid][h * 8 + e]; mx = fmaxf(mx, v[e]); }
            float sum = 0.f;
#pragma unroll
            for (int e = 0; e < 8; e++) { v[e] = __expf(v[e] - mx); sum += v[e]; }
            float inv = 1.f / sum;
#pragma unroll
            for (int e = 0; e < 8; e++) aw[e] += v[e] * inv;
        }
        float* o = &g_aw[((size_t)blockIdx.x * 64 + tid) * 8];
#pragma unroll
        for (int e = 0; e < 8; e++) o[e] = aw[e] * 0.125f;
    }
}

__global__ void gate_kernel() {
    int b = blockIdx.x;
    __shared__ float s[8];
    if (threadIdx.x < 8) s[threadIdx.x] = 0.f;
    __syncthreads();
    const float* p = g_aw + ((size_t)b * L + threadIdx.x) * 8;
    for (int e = 0; e < 8; e++) atomicAdd(&s[e], p[e]);
    __syncthreads();
    if (threadIdx.x == 0) {
        float g[8];
        float mx = -1e30f;
        for (int e = 0; e < 8; e++) { g[e] = s[e] * (1.f / 256.f); mx = fmaxf(mx, g[e]); }
        float sum = 0.f;
        for (int e = 0; e < 8; e++) { g[e] = __expf(g[e] - mx); sum += g[e]; }
        for (int e = 0; e < 8; e++) g[e] /= sum;
        int i0 = 0;
        for (int e = 1; e < 8; e++) if (g[e] > g[i0]) i0 = e;
        int i1 = -1;
        for (int e = 0; e < 8; e++) if (e != i0 && (i1 < 0 || g[e] > g[i1])) i1 = e;
        float mm = fmaxf(g[i0], g[i1]);
        float e0 = __expf(g[i0] - mm), e1 = __expf(g[i1] - mm);
        for (int e = 0; e < 8; e++) g_wsel[e * BATCH + b] = 0.f;
        g_wsel[i0 * BATCH + b] = e0 / (e0 + e1);
        g_wsel[i1 * BATCH + b] = e1 / (e0 + e1);
    }
}

// ---- gated zero of g_y ----
__global__ void zero_y_kernel() {
    int z = blockIdx.y;
    if (g_wsel[z] == 0.f) return;
    float4* p = (float4*)(g_y + (size_t)z * L * DIM);
    int base = blockIdx.x * 256 + threadIdx.x;
#pragma unroll
    for (int i = 0; i < 4; i++)
        p[base + i * 12288] = make_float4(0.f, 0.f, 0.f, 0.f);
}

// ---- fused conv(3x3 dw + silu) + dbl(24 projections): block = (row, z) ----
constexpr int CONVDBL_SMEM = (16 * DIM + 24 * DIM) * 4;

__global__ void __launch_bounds__(768)
conv_dbl_kernel(const float* __restrict__ cw, const float* __restrict__ cb,
                const float* __restrict__ xproj) {
    int z = blockIdx.y;
    if (g_wsel[z] == 0.f) return;
    int e = z >> 4;
    int py = blockIdx.x;
    int tid = threadIdx.x;
    extern __shared__ float smdyn[];
    float* xrow = smdyn;
    float* wsh  = smdyn + 16 * DIM;

    const float* wp = xproj + (size_t)e * 24 * DIM;
    for (int i = tid; i < 24 * DIM; i += 768) wsh[i] = wp[i];

    {
        int c = tid;
        float w[9];
#pragma unroll
        for (int j = 0; j < 9; j++) w[j] = cw[((size_t)e * DIM + c) * 9 + j];
        float bias = cb[e * DIM + c];
        const float* in = g_xz + (size_t)z * L * 2 * DIM + c;
        float* outp = g_xc + (size_t)z * L * DIM + (size_t)py * 16 * DIM + c;

        float v[3][3];
#pragma unroll
        for (int dy = 0; dy < 3; dy++) {
            int y = py - 1 + dy;
            bool yv = (unsigned)y < 16u;
            v[dy][0] = 0.f;
            v[dy][1] = yv ? in[(size_t)(y * 16 + 0) * 2 * DIM] : 0.f;
            v[dy][2] = yv ? in[(size_t)(y * 16 + 1) * 2 * DIM] : 0.f;
        }
#pragma unroll
        for (int px = 0; px < 16; px++) {
            float acc = bias;
#pragma unroll
            for (int dy = 0; dy < 3; dy++)
                acc += v[dy][0] * w[dy * 3] + v[dy][1] * w[dy * 3 + 1] + v[dy][2] * w[dy * 3 + 2];
            float xc = siluf(acc);
            outp[(size_t)px * DIM] = xc;
            xrow[px * DIM + c] = xc;
#pragma unroll
            for (int dy = 0; dy < 3; dy++) {
                int y = py - 1 + dy;
                bool load = ((unsigned)y < 16u) && (px + 2 < 16);
                v[dy][0] = v[dy][1];
                v[dy][1] = v[dy][2];
                v[dy][2] = load ? in[(size_t)(y * 16 + px + 2) * 2 * DIM] : 0.f;
            }
        }
    }
    __syncthreads();

    int wid = tid >> 5, lane = tid & 31;
    const float* wv = wsh + wid * DIM;
#pragma unroll
    for (int px = 0; px < 16; px++) {
        const float* xr = xrow + px * DIM;
        float a = 0.f;
        for (int d = lane; d < DIM; d += 32) a += xr[d] * wv[d];
#pragma unroll
        for (int o = 16; o; o >>= 1) a += __shfl_xor_sync(0xffffffffu, a, o);
        if (lane == 0) {
            int l = py * 16 + px;
            int dir = wid / 6, j = wid % 6;
            int lt = ((l & 15) << 4) | (l >> 4);
            int t = (dir == 0) ? l : (dir == 1) ? (L - 1 - l) : (dir == 2) ? lt : (L - 1 - lt);
            g_dbl[((size_t)(z * 4 + dir) * L + t) * 6 + j] = a;
        }
    }
}

// ---- selective scan: prefetch xv; atomic-accumulate into g_y ----
__global__ void __launch_bounds__(192)
scan_kernel(const float* __restrict__ dtw, const float* __restrict__ dtb,
            const float* __restrict__ Alog, const float* __restrict__ Dp) {
    int z = blockIdx.z;
    if (g_wsel[z] == 0.f) return;
    int e = z >> 4;
    int dir = blockIdx.y;
    int d = blockIdx.x * 192 + threadIdx.x;
    __shared__ float dsh[L * 6];
    const float* xcb = g_xc + (size_t)z * L * DIM;

    const float* db = g_dbl + (size_t)(z * 4 + dir) * L * 6;
    for (int i = threadIdx.x; i < L * 6; i += 192) dsh[i] = db[i];
    __syncthreads();

    int pb = (e * 4 + dir) * DIM + d;
    float w0 = dtw[(size_t)pb * 4 + 0], w1 = dtw[(size_t)pb * 4 + 1];
    float w2 = dtw[(size_t)pb * 4 + 2], w3 = dtw[(size_t)pb * 4 + 3];
    float bb = dtb[pb];
    float A  = -__expf(Alog[pb]);
    float Dv = Dp[pb];
    float hst = 0.f;
    float* yp = g_y + (size_t)z * L * DIM + d;

    int l = dirmap(dir, 0);
    float xv = xcb[(size_t)l * DIM + d];
    for (int t = 0; t < L; t++) {
        int l_n = (t + 1 < L) ? dirmap(dir, t + 1) : 0;
        float xv_n = (t + 1 < L) ? xcb[(size_t)l_n * DIM + d] : 0.f;
        const float* dr = dsh + t * 6;
        float dtl = dr[0] * w0 + dr[1] * w1 + dr[2] * w2 + dr[3] * w3 + bb;
        float dt = softplusf(dtl);
        hst = __expf(dt * A) * hst + (dt * xv) * dr[4];
        atomicAdd(&yp[(size_t)l * DIM], hst * dr[5] + Dv * xv);
        l = l_n;
        xv = xv_n;
    }
}

// ------- finalize: single-stream g_y read -------
__global__ void __launch_bounds__(256)
finalize_kernel(const float* __restrict__ lns, const float* __restrict__ lnb,
                float* __restrict__ out) {
    int z = blockIdx.y;
    float wgt = g_wsel[z];
    if (wgt == 0.f) return;
    int e = z >> 4, b = z & 15;
    int lt0 = blockIdx.x * 16;
    int tid = threadIdx.x;
    int wid = tid >> 5, lane = tid & 31;
    __shared__ float ys[16][DIM];
    __shared__ float smu[16], srs[16];

    const float* yb = g_y + (size_t)z * L * DIM;
    const float* zb = g_xz + (size_t)z * L * 2 * DIM + DIM;

#pragma unroll
    for (int rr = 0; rr < 2; rr++) {
        int li = wid * 2 + rr;
        size_t ro = (size_t)(lt0 + li) * DIM;
        float s = 0.f, ss = 0.f;
        for (int d = lane; d < DIM; d += 32) {
            float v = yb[ro + d];
            ys[li][d] = v;
            s += v; ss += v * v;
        }
#pragma unroll
        for (int o = 16; o; o >>= 1) {
            s  += __shfl_xor_sync(0xffffffffu, s, o);
            ss += __shfl_xor_sync(0xffffffffu, ss, o);
        }
        if (lane == 0) {
            float mu = s * (1.f / 768.f);
            float var = ss * (1.f / 768.f) - mu * mu;
            smu[li] = mu;
            srs[li] = rsqrtf(var + 1e-5f);
        }
    }
    __syncthreads();

    float s0 = lns[e * DIM + tid], s1 = lns[e * DIM + tid + 256], s2 = lns[e * DIM + tid + 512];
    float b0 = lnb[e * DIM + tid], b1 = lnb[e * DIM + tid + 256], b2 = lnb[e * DIM + tid + 512];
    float a0 = 0.f, a1 = 0.f, a2 = 0.f;

#pragma unroll
    for (int li = 0; li < 16; li++) {
        int l = lt0 + li;
        float mu = smu[li], rstd = srs[li];
        float y0 = ys[li][tid], y1 = ys[li][tid + 256], y2 = ys[li][tid + 512];
        float z0 = zb[(size_t)l * 2 * DIM + tid];
        float z1 = zb[(size_t)l * 2 * DIM + tid + 256];
        float z2 = zb[(size_t)l * 2 * DIM + tid + 512];
        a0 += ((y0 - mu) * rstd * s0 + b0) * siluf(z0);
        a1 += ((y1 - mu) * rstd * s1 + b1) * siluf(z1);
        a2 += ((y2 - mu) * rstd * s2 + b2) * siluf(z2);
    }
    float sc = wgt * (1.f / 256.f);
    atomicAdd(&out[b * DIM + tid],       a0 * sc);
    atomicAdd(&out[b * DIM + tid + 256], a1 * sc);
    atomicAdd(&out[b * DIM + tid + 512], a2 * sc);
}

__global__ void zero_kernel(float* __restrict__ out, int n) {
    int i = blockIdx.x * blockDim.x + threadIdx.x;
    if (i < n) out[i] = 0.f;
}

// ---------------- host launcher ----------------
extern "C" void kernel_launch(void* const* d_in, const int* in_sizes, int n_in,
                              void* d_out, int out_size) {
    const float* x         = (const float*)d_in[0];
    const float* sa_in_w   = (const float*)d_in[1];
    const float* sa_in_b   = (const float*)d_in[2];
    const float* sa_out_w  = (const float*)d_in[3];
    const float* sa_out_b  = (const float*)d_in[4];
    const float* ca_in_w   = (const float*)d_in[5];
    const float* ca_in_b   = (const float*)d_in[6];
    const float* eq        = (const float*)d_in[7];
    const float* e_in_w    = (const float*)d_in[8];
    const float* e_in_b    = (const float*)d_in[9];
    const float* e_conv_w  = (const float*)d_in[10];
    const float* e_conv_b  = (const float*)d_in[11];
    const float* e_xproj_w = (const float*)d_in[12];
    const float* e_dtw     = (const float*)d_in[13];
    const float* e_dtb     = (const float*)d_in[14];
    const float* e_Alog    = (const float*)d_in[15];
    const float* e_D       = (const float*)d_in[16];
    const float* e_lns     = (const float*)d_in[17];
    const float* e_lnb     = (const float*)d_in[18];
    float* out = (float*)d_out;

    float* qkv;
    cudaGetSymbolAddress((void**)&qkv, g_qkv);

    cudaFuncSetAttribute(attn_kernel, cudaFuncAttributeMaxDynamicSharedMemorySize, ATTN_SMEM);
    cudaFuncSetAttribute(conv_dbl_kernel, cudaFuncAttributeMaxDynamicSharedMemorySize, CONVDBL_SMEM);

    // gating chain
    gating_pre<<<dim3(64, 3), 256>>>(eq, ca_in_w, ca_in_b);
    vqc_kernel<<<64, 256>>>(ca_in_b, sa_out_b);
    vq2_kernel<<<DIM / 64, 256>>>(sa_out_w);
    gemm_tf32_plain<<<dim3(3 * DIM / 128, BATCH * L / 128), 256>>>(x, sa_in_w, sa_in_b, qkv, DIM, 3 * DIM);
    attn_kernel<<<dim3(NH, BATCH, 4), 256, ATTN_SMEM>>>();
    scores_kernel<<<BATCH * L / 64, 256>>>();
    gate_kernel<<<BATCH, 256>>>();

    // experts (gated per (e,b) on g_wsel)
    zero_kernel<<<(BATCH * DIM + 255) / 256, 256>>>(out, BATCH * DIM);
    zero_y_kernel<<<dim3(48, EB), 256>>>();
    gemm_xz_tf32<<<dim3(2 * DIM / 128, L / 128, EB), 256>>>(x, e_in_w, e_in_b);
    conv_dbl_kernel<<<dim3(16, EB), 768, CONVDBL_SMEM>>>(e_conv_w, e_conv_b, e_xproj_w);
    scan_kernel<<<dim3(4, 4, EB), 192>>>(e_dtw, e_dtb, e_Alog, e_D);
    finalize_kernel<<<dim3(L / 16, EB), 256>>>(e_lns, e_lnb, out);
}

// round 17
// speedup vs baseline: 1.0672x; 1.0672x over previous
#include <cuda_runtime.h>
#include <math.h>
#include <stdint.h>

// ---------------- problem constants ----------------
constexpr int BATCH = 16;
constexpr int L     = 256;      // H*W
constexpr int DIM   = 768;
constexpr int NH    = 8;
constexpr int HD    = 96;
constexpr int NEXP  = 8;
constexpr int EB    = NEXP * BATCH;   // 128 (expert, batch) pairs
constexpr float SCALE = 0.102062072615966f; // 1/sqrt(96)

// ---------------- device scratch (static; no allocation) ----------------
__device__ float g_qkv   [BATCH * L * 3 * DIM];
__device__ float g_ctx   [BATCH * L * DIM];
__device__ float g_k2    [NEXP * DIM];
__device__ float g_u     [64 * DIM];
__device__ float g_qvec  [64 * DIM];
__device__ float g_const [64];
__device__ float g_aw    [BATCH * L * NEXP];
__device__ float g_wsel  [EB];
__device__ float g_xz    [EB * L * 2 * DIM];
__device__ float g_xc    [EB * L * DIM];
__device__ float g_dbl   [EB * 4 * L * 6];
__device__ float g_y     [(size_t)EB * L * DIM];

// ---------------- helpers ----------------
__device__ __forceinline__ float siluf(float x) { return x / (1.f + __expf(-x)); }
__device__ __forceinline__ float softplusf(float x) {
    return (x > 20.f) ? x : __logf(1.f + __expf(x));
}
__device__ __forceinline__ int dirmap(int dir, int t) {
    int tt = (dir & 1) ? (L - 1 - t) : t;
    if (dir < 2) return tt;
    return ((tt & 15) << 4) | (tt >> 4);
}
__device__ __forceinline__ uint32_t f2tf32(float f) {
    uint32_t u;
    asm("cvt.rna.tf32.f32 %0, %1;" : "=r"(u) : "f"(f));
    return u;
}
__device__ __forceinline__ void mma_tf32(float* c, uint32_t a0, uint32_t a1,
                                         uint32_t a2, uint32_t a3,
                                         uint32_t b0, uint32_t b1) {
    asm volatile(
        "mma.sync.aligned.m16n8k8.row.col.f32.tf32.tf32.f32 "
        "{%0,%1,%2,%3}, {%4,%5,%6,%7}, {%8,%9}, {%0,%1,%2,%3};"
        : "+f"(c[0]), "+f"(c[1]), "+f"(c[2]), "+f"(c[3])
        : "r"(a0), "r"(a1), "r"(a2), "r"(a3), "r"(b0), "r"(b1));
}

// ------- tf32 128x128 GEMM tile (R13 form: register double-buffer, pitch-20) -------
__device__ __forceinline__ void gemm128_tf32(const float* __restrict__ A,
                                             const float* __restrict__ Wt,
                                             const float* __restrict__ bias,
                                             float* __restrict__ C,
                                             int K, int ldc) {
    __shared__ uint32_t As[2][128][20];
    __shared__ uint32_t Bs[2][128][20];

    const int tid  = threadIdx.x;
    const int wid  = tid >> 5, lane = tid & 31;
    const int mw   = wid & 1, nw = wid >> 1;
    const int m0   = mw * 64, n0 = nw * 32;
    const int r    = lane >> 2, c4 = lane & 3;
    const int lrow0 = tid >> 2;
    const int lrow1 = lrow0 + 64;
    const int lkc   = (tid & 3) << 2;

    float acc[4][4][4];
#pragma unroll
    for (int i = 0; i < 4; i++)
#pragma unroll
        for (int j = 0; j < 4; j++)
#pragma unroll
            for (int q = 0; q < 4; q++) acc[i][j][q] = 0.f;

    float4 pa0, pa1, pb0, pb1;
    pa0 = *(const float4*)&A [(size_t)lrow0 * K + lkc];
    pa1 = *(const float4*)&A [(size_t)lrow1 * K + lkc];
    pb0 = *(const float4*)&Wt[(size_t)lrow0 * K + lkc];
    pb1 = *(const float4*)&Wt[(size_t)lrow1 * K + lkc];
    As[0][lrow0][lkc + 0] = f2tf32(pa0.x); As[0][lrow0][lkc + 1] = f2tf32(pa0.y);
    As[0][lrow0][lkc + 2] = f2tf32(pa0.z); As[0][lrow0][lkc + 3] = f2tf32(pa0.w);
    As[0][lrow1][lkc + 0] = f2tf32(pa1.x); As[0][lrow1][lkc + 1] = f2tf32(pa1.y);
    As[0][lrow1][lkc + 2] = f2tf32(pa1.z); As[0][lrow1][lkc + 3] = f2tf32(pa1.w);
    Bs[0][lrow0][lkc + 0] = f2tf32(pb0.x); Bs[0][lrow0][lkc + 1] = f2tf32(pb0.y);
    Bs[0][lrow0][lkc + 2] = f2tf32(pb0.z); Bs[0][lrow0][lkc + 3] = f2tf32(pb0.w);
    Bs[0][lrow1][lkc + 0] = f2tf32(pb1.x); Bs[0][lrow1][lkc + 1] = f2tf32(pb1.y);
    Bs[0][lrow1][lkc + 2] = f2tf32(pb1.z); Bs[0][lrow1][lkc + 3] = f2tf32(pb1.w);
    __syncthreads();

    int buf = 0;
    for (int k0 = 16; k0 <= K; k0 += 16) {
        if (k0 < K) {
            pa0 = *(const float4*)&A [(size_t)lrow0 * K + k0 + lkc];
            pa1 = *(const float4*)&A [(size_t)lrow1 * K + k0 + lkc];
            pb0 = *(const float4*)&Wt[(size_t)lrow0 * K + k0 + lkc];
            pb1 = *(const float4*)&Wt[(size_t)lrow1 * K + k0 + lkc];
        }
#pragma unroll
        for (int kk = 0; kk < 16; kk += 8) {
            uint32_t bf0[4], bf1[4];
#pragma unroll
            for (int fn = 0; fn < 4; fn++) {
                bf0[fn] = Bs[buf][n0 + fn * 8 + r][kk + c4];
                bf1[fn] = Bs[buf][n0 + fn * 8 + r][kk + 4 + c4];
            }
#pragma unroll
            for (int fm = 0; fm < 4; fm++) {
                uint32_t a0 = As[buf][m0 + fm * 16 + r    ][kk + c4];
                uint32_t a1 = As[buf][m0 + fm * 16 + r + 8][kk + c4];
                uint32_t a2 = As[buf][m0 + fm * 16 + r    ][kk + 4 + c4];
                uint32_t a3 = As[buf][m0 + fm * 16 + r + 8][kk + 4 + c4];
#pragma unroll
                for (int fn = 0; fn < 4; fn++)
                    mma_tf32(acc[fm][fn], a0, a1, a2, a3, bf0[fn], bf1[fn]);
            }
        }
        if (k0 < K) {
            int nb = buf ^ 1;
            As[nb][lrow0][lkc + 0] = f2tf32(pa0.x); As[nb][lrow0][lkc + 1] = f2tf32(pa0.y);
            As[nb][lrow0][lkc + 2] = f2tf32(pa0.z); As[nb][lrow0][lkc + 3] = f2tf32(pa0.w);
            As[nb][lrow1][lkc + 0] = f2tf32(pa1.x); As[nb][lrow1][lkc + 1] = f2tf32(pa1.y);
            As[nb][lrow1][lkc + 2] = f2tf32(pa1.z); As[nb][lrow1][lkc + 3] = f2tf32(pa1.w);
            Bs[nb][lrow0][lkc + 0] = f2tf32(pb0.x); Bs[nb][lrow0][lkc + 1] = f2tf32(pb0.y);
            Bs[nb][lrow0][lkc + 2] = f2tf32(pb0.z); Bs[nb][lrow0][lkc + 3] = f2tf32(pb0.w);
            Bs[nb][lrow1][lkc + 0] = f2tf32(pb1.x); Bs[nb][lrow1][lkc + 1] = f2tf32(pb1.y);
            Bs[nb][lrow1][lkc + 2] = f2tf32(pb1.z); Bs[nb][lrow1][lkc + 3] = f2tf32(pb1.w);
            __syncthreads();
            buf = nb;
        }
    }

#pragma unroll
    for (int fm = 0; fm < 4; fm++) {
#pragma unroll
        for (int fn = 0; fn < 4; fn++) {
            int rl = m0 + fm * 16 + r;
            int cl = n0 + fn * 8 + (lane & 3) * 2;
            float2 v0, v1;
            v0.x = acc[fm][fn][0] + bias[cl];
            v0.y = acc[fm][fn][1] + bias[cl + 1];
            v1.x = acc[fm][fn][2] + bias[cl];
            v1.y = acc[fm][fn][3] + bias[cl + 1];
            *(float2*)&C[(size_t)rl * ldc + cl]       = v0;
            *(float2*)&C[(size_t)(rl + 8) * ldc + cl] = v1;
        }
    }
}

__global__ void __launch_bounds__(256, 2)
gemm_tf32_plain(const float* __restrict__ A, const float* __restrict__ Wt,
                const float* __restrict__ bias, float* __restrict__ C, int K, int N) {
    gemm128_tf32(A + (size_t)blockIdx.y * 128 * K,
                 Wt + (size_t)blockIdx.x * 128 * K,
                 bias + blockIdx.x * 128,
                 C + (size_t)blockIdx.y * 128 * N + blockIdx.x * 128, K, N);
}

__global__ void __launch_bounds__(256, 2)
gemm_xz_tf32(const float* __restrict__ x, const float* __restrict__ ew,
             const float* __restrict__ eb) {
    int z = blockIdx.z;
    if (g_wsel[z] == 0.f) return;
    int e = z >> 4, b = z & 15;
    gemm128_tf32(x + ((size_t)b * L + blockIdx.y * 128) * DIM,
                 ew + ((size_t)e * 2 * DIM + blockIdx.x * 128) * DIM,
                 eb + e * 2 * DIM + blockIdx.x * 128,
                 g_xz + (size_t)z * L * 2 * DIM
                      + (size_t)blockIdx.y * 128 * 2 * DIM + blockIdx.x * 128,
                 DIM, 2 * DIM);
}

// ---- flash-style tf32 attention: 64-query tiles (unchanged) ----
constexpr int ATTN_SMEM = (6400 + 6400 + 6528 + 4352 + 64) * 4;

__global__ void __launch_bounds__(256) attn_kernel() {
    const int h = blockIdx.x, b = blockIdx.y, qt = blockIdx.z;
    extern __shared__ float sm[];
    uint32_t* Qs  = (uint32_t*)sm;
    uint32_t* Ks  = (uint32_t*)(sm + 6400);
    uint32_t* Vt  = (uint32_t*)(sm + 12800);
    float*    Ps  = sm + 19328;
    uint32_t* Psu = (uint32_t*)Ps;
    float*    rsum = sm + 23680;

    const int tid = threadIdx.x;
    const int wid = tid >> 5, lane = tid & 31;
    const int r = lane >> 2;
    const int m0 = (wid & 1) * 32;
    const int nw = wid >> 1;
    const int n1 = nw * 16;
    const int n2 = nw * 24;

    const float* base = g_qkv + (size_t)b * L * 3 * DIM;

    for (int i = tid; i < 64 * 24; i += 256) {
        int row = i / 24, p = (i % 24) * 4;
        float4 v = *(const float4*)&base[(size_t)(qt * 64 + row) * 3 * DIM + h * HD + p];
        uint32_t* d = &Qs[row * 100 + p];
        d[0] = f2tf32(v.x); d[1] = f2tf32(v.y); d[2] = f2tf32(v.z); d[3] = f2tf32(v.w);
    }
    if (tid < 64) rsum[tid] = 0.f;

    float acc2[2][3][4];
#pragma unroll
    for (int i = 0; i < 2; i++)
#pragma unroll
        for (int j = 0; j < 3; j++)
#pragma unroll
            for (int q = 0; q < 4; q++) acc2[i][j][q] = 0.f;

    for (int kt = 0; kt < 4; kt++) {
        __syncthreads();
        for (int i = tid; i < 64 * 24; i += 256) {
            int row = i / 24, p = (i % 24) * 4;
            float4 v = *(const float4*)&base[(size_t)(kt * 64 + row) * 3 * DIM + DIM + h * HD + p];
            uint32_t* d = &Ks[row * 100 + p];
            d[0] = f2tf32(v.x); d[1] = f2tf32(v.y); d[2] = f2tf32(v.z); d[3] = f2tf32(v.w);
        }
        for (int i = tid; i < 64 * 96; i += 256) {
            int key = i / 96, d = i % 96;
            float v = base[(size_t)(kt * 64 + key) * 3 * DIM + 2 * DIM + h * HD + d];
            Vt[d * 68 + key] = f2tf32(v);
        }
        __syncthreads();

        float acc1[2][2][4];
#pragma unroll
        for (int i = 0; i < 2; i++)
#pragma unroll
            for (int j = 0; j < 2; j++)
#pragma unroll
                for (int q = 0; q < 4; q++) acc1[i][j][q] = 0.f;

        for (int kk = 0; kk < 96; kk += 8) {
            uint32_t bf0[2], bf1[2];
#pragma unroll
            for (int fn = 0; fn < 2; fn++) {
                bf0[fn] = Ks[(n1 + fn * 8 + r) * 100 + kk + (lane & 3)];
                bf1[fn] = Ks[(n1 + fn * 8 + r) * 100 + kk + 4 + (lane & 3)];
            }
#pragma unroll
            for (int fm = 0; fm < 2; fm++) {
                uint32_t a0 = Qs[(m0 + fm * 16 + r    ) * 100 + kk + (lane & 3)];
                uint32_t a1 = Qs[(m0 + fm * 16 + r + 8) * 100 + kk + (lane & 3)];
                uint32_t a2 = Qs[(m0 + fm * 16 + r    ) * 100 + kk + 4 + (lane & 3)];
                uint32_t a3 = Qs[(m0 + fm * 16 + r + 8) * 100 + kk + 4 + (lane & 3)];
#pragma unroll
                for (int fn = 0; fn < 2; fn++)
                    mma_tf32(acc1[fm][fn], a0, a1, a2, a3, bf0[fn], bf1[fn]);
            }
        }
#pragma unroll
        for (int fm = 0; fm < 2; fm++) {
#pragma unroll
            for (int fn = 0; fn < 2; fn++) {
                int rl = m0 + fm * 16 + r;
                int cl = n1 + fn * 8 + (lane & 3) * 2;
                Psu[rl * 68 + cl]           = f2tf32(__expf(acc1[fm][fn][0] * SCALE));
                Psu[rl * 68 + cl + 1]       = f2tf32(__expf(acc1[fm][fn][1] * SCALE));
                Psu[(rl + 8) * 68 + cl]     = f2tf32(__expf(acc1[fm][fn][2] * SCALE));
                Psu[(rl + 8) * 68 + cl + 1] = f2tf32(__expf(acc1[fm][fn][3] * SCALE));
            }
        }
        __syncthreads();
        if (tid < 64) {
            float s = 0.f;
            const float* pr = &Ps[tid * 68];
#pragma unroll 8
            for (int k = 0; k < 64; k++) s += pr[k];
            rsum[tid] += s;
        }
        for (int kk = 0; kk < 64; kk += 8) {
            uint32_t bf0[3], bf1[3];
#pragma unroll
            for (int fn = 0; fn < 3; fn++) {
                bf0[fn] = Vt[(n2 + fn * 8 + r) * 68 + kk + (lane & 3)];
                bf1[fn] = Vt[(n2 + fn * 8 + r) * 68 + kk + 4 + (lane & 3)];
            }
#pragma unroll
            for (int fm = 0; fm < 2; fm++) {
                uint32_t a0 = Psu[(m0 + fm * 16 + r    ) * 68 + kk + (lane & 3)];
                uint32_t a1 = Psu[(m0 + fm * 16 + r + 8) * 68 + kk + (lane & 3)];
                uint32_t a2 = Psu[(m0 + fm * 16 + r    ) * 68 + kk + 4 + (lane & 3)];
                uint32_t a3 = Psu[(m0 + fm * 16 + r + 8) * 68 + kk + 4 + (lane & 3)];
#pragma unroll
                for (int fn = 0; fn < 3; fn++)
                    mma_tf32(acc2[fm][fn], a0, a1, a2, a3, bf0[fn], bf1[fn]);
            }
        }
    }
    __syncthreads();

#pragma unroll
    for (int fm = 0; fm < 2; fm++) {
        int rl = m0 + fm * 16 + r;
        float inv0 = 1.f / rsum[rl];
        float inv1 = 1.f / rsum[rl + 8];
        int q0 = qt * 64 + rl;
#pragma unroll
        for (int fn = 0; fn < 3; fn++) {
            int cl = n2 + fn * 8 + (lane & 3) * 2;
            float* o0 = &g_ctx[((size_t)b * L + q0) * DIM + h * HD + cl];
            float* o1 = &g_ctx[((size_t)b * L + q0 + 8) * DIM + h * HD + cl];
            o0[0] = acc2[fm][fn][0] * inv0;
            o0[1] = acc2[fm][fn][1] * inv0;
            o1[0] = acc2[fm][fn][2] * inv1;
            o1[1] = acc2[fm][fn][3] * inv1;
        }
    }
}

// ---- gating precompute: warp-distributed k2 + coalesced u; grid (64, 3) ----
__global__ void __launch_bounds__(256)
gating_pre(const float* __restrict__ eq, const float* __restrict__ ca_w,
           const float* __restrict__ ca_b) {
    int he = blockIdx.x;
    int e = he & 7, h = he >> 3;
    int tid = threadIdx.x;
    int wid = tid >> 5, lane = tid & 31;
    __shared__ float eqs[DIM];
    __shared__ float k2s[HD];

    for (int i = tid; i < DIM; i += 256) eqs[i] = eq[e * DIM + i];
    __syncthreads();

#pragma unroll
    for (int j = 0; j < 12; j++) {
        int d = wid * 12 + j;
        int c = h * HD + d;
        const float* w = ca_w + (size_t)(DIM + c) * DIM;
        float s = 0.f;
#pragma unroll
        for (int k = lane * 4; k < DIM; k += 128) {
            float4 wv = *(const float4*)&w[k];
            s += eqs[k] * wv.x + eqs[k + 1] * wv.y + eqs[k + 2] * wv.z + eqs[k + 3] * wv.w;
        }
#pragma unroll
        for (int o = 16; o; o >>= 1) s += __shfl_xor_sync(0xffffffffu, s, o);
        if (lane == 0) k2s[d] = s + ca_b[DIM + c];
    }
    __syncthreads();

    if (blockIdx.y == 0 && tid < HD) g_k2[e * DIM + h * HD + tid] = k2s[tid];

    int c = blockIdx.y * 256 + tid;
    float s = 0.f;
#pragma unroll 4
    for (int d = 0; d < HD; d++) s += ca_w[(size_t)(h * HD + d) * DIM + c] * k2s[d];
    g_u[(size_t)he * DIM + c] = s;
}

__global__ void __launch_bounds__(256)
vqc_kernel(const float* __restrict__ ca_b, const float* __restrict__ sa_ob) {
    int he = blockIdx.x;
    int e = he & 7, h = he >> 3;
    int tid = threadIdx.x;
    __shared__ float red[256];
    float part = 0.f;
    for (int c = tid; c < DIM; c += 256) part += sa_ob[c] * g_u[(size_t)he * DIM + c];
    if (tid < HD) part += ca_b[h * HD + tid] * g_k2[e * DIM + h * HD + tid];
    red[tid] = part;
    __syncthreads();
    for (int s = 128; s; s >>= 1) {
        if (tid < s) red[tid] += red[tid + s];
        __syncthreads();
    }
    if (tid == 0) g_const[he] = red[0];
}

__global__ void __launch_bounds__(256)
vq2_kernel(const float* __restrict__ sa_ow) {
    __shared__ float Us[16][68];
    __shared__ float Ws[16][68];
    const int tid = threadIdx.x;
    const int tx = tid & 15, ty = tid >> 4;
    const int n0 = blockIdx.x * 64;
    const int row = tid >> 2, kc = (tid & 3) << 2;

    float acc[4][4];
#pragma unroll
    for (int i = 0; i < 4; i++)
#pragma unroll
        for (int j = 0; j < 4; j++) acc[i][j] = 0.f;

    for (int k0 = 0; k0 < DIM; k0 += 16) {
        float4 vu = *(const float4*)&g_u[(size_t)row * DIM + k0 + kc];
        Us[kc + 0][row] = vu.x; Us[kc + 1][row] = vu.y;
        Us[kc + 2][row] = vu.z; Us[kc + 3][row] = vu.w;
        int wk = tid >> 4, wc = (tid & 15) * 4;
        float4 vw = *(const float4*)&sa_ow[(size_t)(k0 + wk) * DIM + n0 + wc];
        Ws[wk][wc + 0] = vw.x; Ws[wk][wc + 1] = vw.y;
        Ws[wk][wc + 2] = vw.z; Ws[wk][wc + 3] = vw.w;
        __syncthreads();
#pragma unroll
        for (int k = 0; k < 16; k++) {
            float a[4], w[4];
            *(float4*)&a[0] = *(const float4*)&Us[k][ty * 4];
            *(float4*)&w[0] = *(const float4*)&Ws[k][tx * 4];
#pragma unroll
            for (int i = 0; i < 4; i++)
#pragma unroll
                for (int j = 0; j < 4; j++) acc[i][j] += a[i] * w[j];
        }
        __syncthreads();
    }
#pragma unroll
    for (int i = 0; i < 4; i++)
#pragma unroll
        for (int j = 0; j < 4; j++)
            g_qvec[(size_t)(ty * 4 + i) * DIM + n0 + tx * 4 + j] = acc[i][j];
}

// scores + per-token softmax over experts + head-mean, fused
__global__ void __launch_bounds__(256)
scores_kernel() {
    __shared__ float As[16][68];
    __shared__ float Qs[16][68];
    __shared__ float Sb[64][65];
    const int tid = threadIdx.x;
    const int tx = tid & 15, ty = tid >> 4;
    const int row = tid >> 2, kc = (tid & 3) << 2;
    const float* A = g_ctx + (size_t)blockIdx.x * 64 * DIM;

    float acc[4][4];
#pragma unroll
    for (int i = 0; i < 4; i++)
#pragma unroll
        for (int j = 0; j < 4; j++) acc[i][j] = 0.f;

    for (int k0 = 0; k0 < DIM; k0 += 16) {
        float4 va = *(const float4*)&A[(size_t)row * DIM + k0 + kc];
        float4 vq = *(const float4*)&g_qvec[(size_t)row * DIM + k0 + kc];
        As[kc + 0][row] = va.x; As[kc + 1][row] = va.y;
        As[kc + 2][row] = va.z; As[kc + 3][row] = va.w;
        Qs[kc + 0][row] = vq.x; Qs[kc + 1][row] = vq.y;
        Qs[kc + 2][row] = vq.z; Qs[kc + 3][row] = vq.w;
        __syncthreads();
#pragma unroll
        for (int k = 0; k < 16; k++) {
            float a[4], q[4];
            *(float4*)&a[0] = *(const float4*)&As[k][ty * 4];
            *(float4*)&q[0] = *(const float4*)&Qs[k][tx * 4];
#pragma unroll
            for (int i = 0; i < 4; i++)
#pragma unroll
                for (int j = 0; j < 4; j++) acc[i][j] += a[i] * q[j];
        }
        __syncthreads();
    }
#pragma unroll
    for (int i = 0; i < 4; i++)
#pragma unroll
        for (int j = 0; j < 4; j++)
            Sb[ty * 4 + i][tx * 4 + j] = (acc[i][j] + g_const[tx * 4 + j]) * SCALE;
    __syncthreads();

    if (tid < 64) {
        float aw[8];
#pragma unroll
        for (int e = 0; e < 8; e++) aw[e] = 0.f;
        for (int h = 0; h < 8; h++) {
            float v[8], mx = -1e30f;
#pragma unroll
            for (int e = 0; e < 8; e++) { v[e] = Sb[tid][h * 8 + e]; mx = fmaxf(mx, v[e]); }
            float sum = 0.f;
#pragma unroll
            for (int e = 0; e < 8; e++) { v[e] = __expf(v[e] - mx); sum += v[e]; }
            float inv = 1.f / sum;
#pragma unroll
            for (int e = 0; e < 8; e++) aw[e] += v[e] * inv;
        }
        float* o = &g_aw[((size_t)blockIdx.x * 64 + tid) * 8];
#pragma unroll
        for (int e = 0; e < 8; e++) o[e] = aw[e] * 0.125f;
    }
}

__global__ void gate_kernel() {
    int b = blockIdx.x;
    __shared__ float s[8];
    if (threadIdx.x < 8) s[threadIdx.x] = 0.f;
    __syncthreads();
    const float* p = g_aw + ((size_t)b * L + threadIdx.x) * 8;
    for (int e = 0; e < 8; e++) atomicAdd(&s[e], p[e]);
    __syncthreads();
    if (threadIdx.x == 0) {
        float g[8];
        float mx = -1e30f;
        for (int e = 0; e < 8; e++) { g[e] = s[e] * (1.f / 256.f); mx = fmaxf(mx, g[e]); }
        float sum = 0.f;
        for (int e = 0; e < 8; e++) { g[e] = __expf(g[e] - mx); sum += g[e]; }
        for (int e = 0; e < 8; e++) g[e] /= sum;
        int i0 = 0;
        for (int e = 1; e < 8; e++) if (g[e] > g[i0]) i0 = e;
        int i1 = -1;
        for (int e = 0; e < 8; e++) if (e != i0 && (i1 < 0 || g[e] > g[i1])) i1 = e;
        float mm = fmaxf(g[i0], g[i1]);
        float e0 = __expf(g[i0] - mm), e1 = __expf(g[i1] - mm);
        for (int e = 0; e < 8; e++) g_wsel[e * BATCH + b] = 0.f;
        g_wsel[i0 * BATCH + b] = e0 / (e0 + e1);
        g_wsel[i1 * BATCH + b] = e1 / (e0 + e1);
    }
}

// ---- UNGATED zero of g_y (runs early on side stream) ----
__global__ void zero_y_kernel() {
    int z = blockIdx.y;
    float4* p = (float4*)(g_y + (size_t)z * L * DIM);
    int base = blockIdx.x * 256 + threadIdx.x;
#pragma unroll
    for (int i = 0; i < 4; i++)
        p[base + i * 12288] = make_float4(0.f, 0.f, 0.f, 0.f);
}

// ---- fused conv(3x3 dw + silu) + dbl(24 projections): block = (row, z) ----
constexpr int CONVDBL_SMEM = (16 * DIM + 24 * DIM) * 4;

__global__ void __launch_bounds__(768)
conv_dbl_kernel(const float* __restrict__ cw, const float* __restrict__ cb,
                const float* __restrict__ xproj) {
    int z = blockIdx.y;
    if (g_wsel[z] == 0.f) return;
    int e = z >> 4;
    int py = blockIdx.x;
    int tid = threadIdx.x;
    extern __shared__ float smdyn[];
    float* xrow = smdyn;
    float* wsh  = smdyn + 16 * DIM;

    const float* wp = xproj + (size_t)e * 24 * DIM;
    for (int i = tid; i < 24 * DIM; i += 768) wsh[i] = wp[i];

    {
        int c = tid;
        float w[9];
#pragma unroll
        for (int j = 0; j < 9; j++) w[j] = cw[((size_t)e * DIM + c) * 9 + j];
        float bias = cb[e * DIM + c];
        const float* in = g_xz + (size_t)z * L * 2 * DIM + c;
        float* outp = g_xc + (size_t)z * L * DIM + (size_t)py * 16 * DIM + c;

        float v[3][3];
#pragma unroll
        for (int dy = 0; dy < 3; dy++) {
            int y = py - 1 + dy;
            bool yv = (unsigned)y < 16u;
            v[dy][0] = 0.f;
            v[dy][1] = yv ? in[(size_t)(y * 16 + 0) * 2 * DIM] : 0.f;
            v[dy][2] = yv ? in[(size_t)(y * 16 + 1) * 2 * DIM] : 0.f;
        }
#pragma unroll
        for (int px = 0; px < 16; px++) {
            float acc = bias;
#pragma unroll
            for (int dy = 0; dy < 3; dy++)
                acc += v[dy][0] * w[dy * 3] + v[dy][1] * w[dy * 3 + 1] + v[dy][2] * w[dy * 3 + 2];
            float xc = siluf(acc);
            outp[(size_t)px * DIM] = xc;
            xrow[px * DIM + c] = xc;
#pragma unroll
            for (int dy = 0; dy < 3; dy++) {
                int y = py - 1 + dy;
                bool load = ((unsigned)y < 16u) && (px + 2 < 16);
                v[dy][0] = v[dy][1];
                v[dy][1] = v[dy][2];
                v[dy][2] = load ? in[(size_t)(y * 16 + px + 2) * 2 * DIM] : 0.f;
            }
        }
    }
    __syncthreads();

    int wid = tid >> 5, lane = tid & 31;
    const float* wv = wsh + wid * DIM;
#pragma unroll
    for (int px = 0; px < 16; px++) {
        const float* xr = xrow + px * DIM;
        float a = 0.f;
        for (int d = lane; d < DIM; d += 32) a += xr[d] * wv[d];
#pragma unroll
        for (int o = 16; o; o >>= 1) a += __shfl_xor_sync(0xffffffffu, a, o);
        if (lane == 0) {
            int l = py * 16 + px;
            int dir = wid / 6, j = wid % 6;
            int lt = ((l & 15) << 4) | (l >> 4);
            int t = (dir == 0) ? l : (dir == 1) ? (L - 1 - l) : (dir == 2) ? lt : (L - 1 - lt);
            g_dbl[((size_t)(z * 4 + dir) * L + t) * 6 + j] = a;
        }
    }
}

// ---- selective scan: prefetch xv; atomic-accumulate into g_y ----
__global__ void __launch_bounds__(192)
scan_kernel(const float* __restrict__ dtw, const float* __restrict__ dtb,
            const float* __restrict__ Alog, const float* __restrict__ Dp) {
    int z = blockIdx.z;
    if (g_wsel[z] == 0.f) return;
    int e = z >> 4;
    int dir = blockIdx.y;
    int d = blockIdx.x * 192 + threadIdx.x;
    __shared__ float dsh[L * 6];
    const float* xcb = g_xc + (size_t)z * L * DIM;

    const float* db = g_dbl + (size_t)(z * 4 + dir) * L * 6;
    for (int i = threadIdx.x; i < L * 6; i += 192) dsh[i] = db[i];
    __syncthreads();

    int pb = (e * 4 + dir) * DIM + d;
    float w0 = dtw[(size_t)pb * 4 + 0], w1 = dtw[(size_t)pb * 4 + 1];
    float w2 = dtw[(size_t)pb * 4 + 2], w3 = dtw[(size_t)pb * 4 + 3];
    float bb = dtb[pb];
    float A  = -__expf(Alog[pb]);
    float Dv = Dp[pb];
    float hst = 0.f;
    float* yp = g_y + (size_t)z * L * DIM + d;

    int l = dirmap(dir, 0);
    float xv = xcb[(size_t)l * DIM + d];
    for (int t = 0; t < L; t++) {
        int l_n = (t + 1 < L) ? dirmap(dir, t + 1) : 0;
        float xv_n = (t + 1 < L) ? xcb[(size_t)l_n * DIM + d] : 0.f;
        const float* dr = dsh + t * 6;
        float dtl = dr[0] * w0 + dr[1] * w1 + dr[2] * w2 + dr[3] * w3 + bb;
        float dt = softplusf(dtl);
        hst = __expf(dt * A) * hst + (dt * xv) * dr[4];
        atomicAdd(&yp[(size_t)l * DIM], hst * dr[5] + Dv * xv);
        l = l_n;
        xv = xv_n;
    }
}

// ------- finalize: single-stream g_y read -------
__global__ void __launch_bounds__(256)
finalize_kernel(const float* __restrict__ lns, const float* __restrict__ lnb,
                float* __restrict__ out) {
    int z = blockIdx.y;
    float wgt = g_wsel[z];
    if (wgt == 0.f) return;
    int e = z >> 4, b = z & 15;
    int lt0 = blockIdx.x * 16;
    int tid = threadIdx.x;
    int wid = tid >> 5, lane = tid & 31;
    __shared__ float ys[16][DIM];
    __shared__ float smu[16], srs[16];

    const float* yb = g_y + (size_t)z * L * DIM;
    const float* zb = g_xz + (size_t)z * L * 2 * DIM + DIM;

#pragma unroll
    for (int rr = 0; rr < 2; rr++) {
        int li = wid * 2 + rr;
        size_t ro = (size_t)(lt0 + li) * DIM;
        float s = 0.f, ss = 0.f;
        for (int d = lane; d < DIM; d += 32) {
            float v = yb[ro + d];
            ys[li][d] = v;
            s += v; ss += v * v;
        }
#pragma unroll
        for (int o = 16; o; o >>= 1) {
            s  += __shfl_xor_sync(0xffffffffu, s, o);
            ss += __shfl_xor_sync(0xffffffffu, ss, o);
        }
        if (lane == 0) {
            float mu = s * (1.f / 768.f);
            float var = ss * (1.f / 768.f) - mu * mu;
            smu[li] = mu;
            srs[li] = rsqrtf(var + 1e-5f);
        }
    }
    __syncthreads();

    float s0 = lns[e * DIM + tid], s1 = lns[e * DIM + tid + 256], s2 = lns[e * DIM + tid + 512];
    float b0 = lnb[e * DIM + tid], b1 = lnb[e * DIM + tid + 256], b2 = lnb[e * DIM + tid + 512];
    float a0 = 0.f, a1 = 0.f, a2 = 0.f;

#pragma unroll
    for (int li = 0; li < 16; li++) {
        int l = lt0 + li;
        float mu = smu[li], rstd = srs[li];
        float y0 = ys[li][tid], y1 = ys[li][tid + 256], y2 = ys[li][tid + 512];
        float z0 = zb[(size_t)l * 2 * DIM + tid];
        float z1 = zb[(size_t)l * 2 * DIM + tid + 256];
        float z2 = zb[(size_t)l * 2 * DIM + tid + 512];
        a0 += ((y0 - mu) * rstd * s0 + b0) * siluf(z0);
        a1 += ((y1 - mu) * rstd * s1 + b1) * siluf(z1);
        a2 += ((y2 - mu) * rstd * s2 + b2) * siluf(z2);
    }
    float sc = wgt * (1.f / 256.f);
    atomicAdd(&out[b * DIM + tid],       a0 * sc);
    atomicAdd(&out[b * DIM + tid + 256], a1 * sc);
    atomicAdd(&out[b * DIM + tid + 512], a2 * sc);
}

__global__ void zero_kernel(float* __restrict__ out, int n) {
    int i = blockIdx.x * blockDim.x + threadIdx.x;
    if (i < n) out[i] = 0.f;
}

// ---------------- host launcher: fork-join dual-stream graph ----------------
extern "C" void kernel_launch(void* const* d_in, const int* in_sizes, int n_in,
                              void* d_out, int out_size) {
    const float* x         = (const float*)d_in[0];
    const float* sa_in_w   = (const float*)d_in[1];
    const float* sa_in_b   = (const float*)d_in[2];
    const float* sa_out_w  = (const float*)d_in[3];
    const float* sa_out_b  = (const float*)d_in[4];
    const float* ca_in_w   = (const float*)d_in[5];
    const float* ca_in_b   = (const float*)d_in[6];
    const float* eq        = (const float*)d_in[7];
    const float* e_in_w    = (const float*)d_in[8];
    const float* e_in_b    = (const float*)d_in[9];
    const float* e_conv_w  = (const float*)d_in[10];
    const float* e_conv_b  = (const float*)d_in[11];
    const float* e_xproj_w = (const float*)d_in[12];
    const float* e_dtw     = (const float*)d_in[13];
    const float* e_dtb     = (const float*)d_in[14];
    const float* e_Alog    = (const float*)d_in[15];
    const float* e_D       = (const float*)d_in[16];
    const float* e_lns     = (const float*)d_in[17];
    const float* e_lnb     = (const float*)d_in[18];
    float* out = (float*)d_out;

    float* qkv;
    cudaGetSymbolAddress((void**)&qkv, g_qkv);

    cudaFuncSetAttribute(attn_kernel, cudaFuncAttributeMaxDynamicSharedMemorySize, ATTN_SMEM);
    cudaFuncSetAttribute(conv_dbl_kernel, cudaFuncAttributeMaxDynamicSharedMemorySize, CONVDBL_SMEM);

    // side stream + fork/join events (created per call; harness calls this
    // only for correctness + capture, so no unbounded resource growth)
    cudaStream_t s2;
    cudaEvent_t evFork, evJoin;
    cudaStreamCreateWithFlags(&s2, cudaStreamNonBlocking);
    cudaEventCreateWithFlags(&evFork, cudaEventDisableTiming);
    cudaEventCreateWithFlags(&evJoin, cudaEventDisableTiming);

    // fork: side stream does gating precompute + zeroing under qkv/attn shadow
    cudaEventRecord(evFork, 0);
    cudaStreamWaitEvent(s2, evFork, 0);

    zero_kernel<<<(BATCH * DIM + 255) / 256, 256, 0, s2>>>(out, BATCH * DIM);
    zero_y_kernel<<<dim3(48, EB), 256, 0, s2>>>();
    gating_pre<<<dim3(64, 3), 256, 0, s2>>>(eq, ca_in_w, ca_in_b);
    vqc_kernel<<<64, 256, 0, s2>>>(ca_in_b, sa_out_b);
    vq2_kernel<<<DIM / 64, 256, 0, s2>>>(sa_out_w);
    cudaEventRecord(evJoin, s2);

    // main stream: qkv GEMM + attention
    gemm_tf32_plain<<<dim3(3 * DIM / 128, BATCH * L / 128), 256>>>(x, sa_in_w, sa_in_b, qkv, DIM, 3 * DIM);
    attn_kernel<<<dim3(NH, BATCH, 4), 256, ATTN_SMEM>>>();

    // join: scores needs ctx (main) + qvec/const (s2)
    cudaStreamWaitEvent(0, evJoin, 0);
    scores_kernel<<<BATCH * L / 64, 256>>>();
    gate_kernel<<<BATCH, 256>>>();

    // experts (gated per (e,b) on g_wsel)
    gemm_xz_tf32<<<dim3(2 * DIM / 128, L / 128, EB), 256>>>(x, e_in_w, e_in_b);
    conv_dbl_kernel<<<dim3(16, EB), 768, CONVDBL_SMEM>>>(e_conv_w, e_conv_b, e_xproj_w);
    scan_kernel<<<dim3(4, 4, EB), 192>>>(e_dtw, e_dtb, e_Alog, e_D);
    finalize_kernel<<<dim3(L / 16, EB), 256>>>(e_lns, e_lnb, out);
}